// round 2
// baseline (speedup 1.0000x reference)
#include <cuda_runtime.h>

// Per-program lookup: each COEFFS row has at most 2 nonzero coefficients.
// plane index: 0 = hearts plane0, 1 = hearts plane1, 2 = rects plane0, 3 = rects plane1
// For single-plane programs, plane B aliases plane A with coeff 0 (L1-hit, free).
__constant__ int   d_planeA[9] = { 0, 2, 0, 0, 2, 0, 0, 0, 2 };
__constant__ float d_cA[9]     = { 1.f, 1.f, 1.f, 1.f, 1.f, 1.f, 1.f, -1.f, 1.f };
__constant__ int   d_planeB[9] = { 0, 2, 2, 1, 3, 1, 2, 2, 3 };
__constant__ float d_cB[9]     = { 0.f, 0.f, 1.f, 1.f, 1.f, -1.f, -1.f, 1.f, -1.f };

// One block = one (i,j) pair = one 64x64 output tile (4096 floats = 1024 float4).
// 256 threads x 4 unrolled iterations x float4.
__global__ __launch_bounds__(256)
void tgm_kernel(const int* __restrict__ program_id,
                const float* __restrict__ hearts,
                const float* __restrict__ rects,
                float* __restrict__ out)
{
    const int b = blockIdx.x;            // 0..8191
    const int p = __ldg(program_id + b); // block-uniform

    const float cA = d_cA[p];
    const float cB = d_cB[p];
    const int   pA = d_planeA[p];
    const int   pB = d_planeB[p];

    // plane base: hearts for idx<2, rects for idx>=2; plane1 offset = 4096 floats
    const float* baseA = ((pA < 2) ? hearts : rects) + (size_t)b * 8192 + (size_t)(pA & 1) * 4096;
    const float* baseB = ((pB < 2) ? hearts : rects) + (size_t)b * 8192 + (size_t)(pB & 1) * 4096;

    const float4* __restrict__ A = (const float4*)baseA;
    const float4* __restrict__ B = (const float4*)baseB;
    float4* __restrict__ o = (float4*)(out + (size_t)b * 4096);

    const int t = threadIdx.x;

    // Front-batch all loads for maximal MLP, then compute, then store.
    float4 va[4], vb[4];
    #pragma unroll
    for (int k = 0; k < 4; ++k) {
        va[k] = __ldg(&A[t + k * 256]);
    }
    #pragma unroll
    for (int k = 0; k < 4; ++k) {
        vb[k] = __ldg(&B[t + k * 256]);
    }

    #pragma unroll
    for (int k = 0; k < 4; ++k) {
        float4 a;
        a.x = fmaf(cA, va[k].x, cB * vb[k].x);
        a.y = fmaf(cA, va[k].y, cB * vb[k].y);
        a.z = fmaf(cA, va[k].z, cB * vb[k].z);
        a.w = fmaf(cA, va[k].w, cB * vb[k].w);

        a.x = fminf(fmaxf(a.x, 0.0f), 1.0f);
        a.y = fminf(fmaxf(a.y, 0.0f), 1.0f);
        a.z = fminf(fmaxf(a.z, 0.0f), 1.0f);
        a.w = fminf(fmaxf(a.w, 0.0f), 1.0f);

        o[t + k * 256] = a;
    }
}

extern "C" void kernel_launch(void* const* d_in, const int* in_sizes, int n_in,
                              void* d_out, int out_size)
{
    const int*   program_id = (const int*)  d_in[0]; // [128,64] int32
    const float* hearts     = (const float*)d_in[1]; // [128,64,2,64,64] f32
    const float* rects      = (const float*)d_in[2]; // [128,64,2,64,64] f32
    float*       out        = (float*)d_out;         // [128,64,64,64] f32

    const int n_pairs = in_sizes[0];                 // 8192 blocks, one per (i,j)
    tgm_kernel<<<n_pairs, 256>>>(program_id, hearts, rects, out);
}